// round 8
// baseline (speedup 1.0000x reference)
#include <cuda_runtime.h>
#include <cuda_fp16.h>
#include <cstdint>

#define Bdim 8
#define Ndim 512
#define Sdim 4096
#define Hdim 1024

#define BM 128
#define BN 128
#define BK 64
#define STAGES 3
#define NKITER (Sdim / BK)          // 64
#define NTILES 256
#define NCTAS 148
#define NTHREADS 512                 // 256 GEMM + 256 cvt
#define GEMM_T 256
#define CVT_T 256
#define CVT_NTHR (NCTAS * CVT_T)     // 37888

#define DOC_CH_B ((Sdim * Hdim) / 8)   // 524288 chunks of 8 floats
#define MAP_CH_B ((Ndim * Sdim) / 8)   // 262144

#define A_ROW_B 144                  // 64 halves (128B) + 16B pad
#define B_ROW_B 272                  // 128 halves (256B) + 16B pad
#define A_STAGE_B (BM * A_ROW_B)     // 18432 B
#define B_STAGE_B (BK * B_ROW_B)     // 17408 B
#define STAGE_B   (A_STAGE_B + B_STAGE_B)   // 35840 B
#define DYN_SMEM  (STAGES * STAGE_B)        // 107520 B

// fp16 scratch + sync state (static device globals -- allowed scratch path)
__device__ __align__(16) __half g_doc_h[(size_t)Bdim * Sdim * Hdim];  // 67.1 MB
__device__ __align__(16) __half g_map_h[(size_t)Bdim * Ndim * Sdim];  // 33.6 MB
__device__ int g_count[Bdim];
__device__ int g_flag[Bdim];

__device__ __forceinline__ uint32_t smem_u32(const void* p) {
    uint32_t a;
    asm("{ .reg .u64 t; cvta.to.shared.u64 t, %1; cvt.u32.u64 %0, t; }" : "=r"(a) : "l"(p));
    return a;
}
__device__ __forceinline__ void cp16(uint32_t sdst, const void* gsrc) {
    asm volatile("cp.async.cg.shared.global [%0], [%1], 16;" :: "r"(sdst), "l"(gsrc));
}
__device__ __forceinline__ uint32_t h2u(__half2 h) {
    return *reinterpret_cast<uint32_t*>(&h);
}
#define GSYNC() asm volatile("bar.sync 1, %0;" :: "r"(GEMM_T) : "memory")
#define CSYNC() asm volatile("bar.sync 2, %0;" :: "r"(CVT_T) : "memory")

__global__ void reset_flags() {
    if (threadIdx.x < Bdim) {
        g_count[threadIdx.x] = 0;
        g_flag[threadIdx.x] = 0;
    }
    __threadfence();
}

__global__ void __launch_bounds__(NTHREADS, 1)
fused_pool(const float* __restrict__ doc,   // [B,S,H] fp32
           const float* __restrict__ map,   // [B,N,S] fp32
           const float* __restrict__ lens,  // [B,N]
           float* __restrict__ out)         // [B,N,H]
{
    extern __shared__ char smraw[];
    const int tid = threadIdx.x;

    // ================= CVT role: threads 256..511 =================
    if (tid >= GEMM_T) {
        const int ct = blockIdx.x * CVT_T + (tid - GEMM_T);
        for (int b = 0; b < Bdim; b++) {
            {
                const float4* s4 = (const float4*)(doc + (size_t)b * Sdim * Hdim);
                uint4* d4 = (uint4*)(g_doc_h + (size_t)b * Sdim * Hdim);
                for (int i = ct; i < DOC_CH_B; i += CVT_NTHR) {
                    const float4 v0 = s4[2 * i];
                    const float4 v1 = s4[2 * i + 1];
                    uint4 o;
                    o.x = h2u(__floats2half2_rn(v0.x, v0.y));
                    o.y = h2u(__floats2half2_rn(v0.z, v0.w));
                    o.z = h2u(__floats2half2_rn(v1.x, v1.y));
                    o.w = h2u(__floats2half2_rn(v1.z, v1.w));
                    d4[i] = o;
                }
            }
            {
                const float4* s4 = (const float4*)(map + (size_t)b * Ndim * Sdim);
                uint4* d4 = (uint4*)(g_map_h + (size_t)b * Ndim * Sdim);
                for (int i = ct; i < MAP_CH_B; i += CVT_NTHR) {
                    const float4 v0 = s4[2 * i];
                    const float4 v1 = s4[2 * i + 1];
                    uint4 o;
                    o.x = h2u(__floats2half2_rn(v0.x, v0.y));
                    o.y = h2u(__floats2half2_rn(v0.z, v0.w));
                    o.z = h2u(__floats2half2_rn(v1.x, v1.y));
                    o.w = h2u(__floats2half2_rn(v1.z, v1.w));
                    d4[i] = o;
                }
            }
            __threadfence();
            CSYNC();
            if (tid == GEMM_T) {
                if (atomicAdd(&g_count[b], 1) == NCTAS - 1) {
                    __threadfence();
                    atomicExch(&g_flag[b], 1);   // release batch b
                }
            }
        }
        return;
    }

    // ================= GEMM role: threads 0..255 (8 warps) =================
    const int lane = tid & 31;
    const int w    = tid >> 5;
    const int wm   = w & 3;          // 4 warps along M (32 rows each)
    const int wn   = w >> 2;         // 2 warps along N (64 cols each)

    const uint32_t sbase = smem_u32(smraw);

    // ldmatrix lane address components
    const int t8 = lane >> 3;
    const int r8 = lane & 7;
    const uint32_t a_lane_off =
        (uint32_t)(((t8 & 1) * 8 + r8) * A_ROW_B + (t8 >> 1) * 16);
    const uint32_t b_lane_off =
        (uint32_t)(((t8 & 1) * 8 + r8) * B_ROW_B + (t8 >> 1) * 16);
    const int gid = lane >> 2, tq = lane & 3;

    for (int t = blockIdx.x; t < NTILES; t += NCTAS) {
        const int b  = t >> 5;
        const int m0 = ((t >> 3) & 3) * BM;
        const int h0 = (t & 7) * BN;

        // wait for batch b to be converted
        if (tid == 0) {
            int v;
            do {
                v = atomicAdd(&g_flag[b], 0);
                if (!v) __nanosleep(512);
            } while (!v);
        }
        GSYNC();   // also separates previous tile's smem use from this prologue

        const __half* Ag = g_map_h + (size_t)b * Ndim * Sdim + (size_t)m0 * Sdim;
        const __half* Bg = g_doc_h + (size_t)b * Sdim * Hdim + h0;

        auto load_stage = [&](int st, int k0) {
            const uint32_t abase = sbase + (uint32_t)(st * STAGE_B);
            const uint32_t bbase = abase + A_STAGE_B;
            #pragma unroll
            for (int i = 0; i < 4; i++) {          // A: 1024 16B-chunks
                const int c = tid + GEMM_T * i;
                const int m = c >> 3, q = c & 7;
                cp16(abase + (uint32_t)(m * A_ROW_B + q * 16),
                     Ag + (size_t)m * Sdim + k0 + q * 8);
            }
            #pragma unroll
            for (int i = 0; i < 4; i++) {          // B: 1024 16B-chunks
                const int c = tid + GEMM_T * i;
                const int k = c >> 4, q = c & 15;
                cp16(bbase + (uint32_t)(k * B_ROW_B + q * 16),
                     Bg + (size_t)(k0 + k) * Hdim + q * 8);
            }
        };

        float acc[2][8][4];
        #pragma unroll
        for (int i = 0; i < 2; i++)
            #pragma unroll
            for (int j = 0; j < 8; j++)
                #pragma unroll
                for (int r = 0; r < 4; r++)
                    acc[i][j][r] = 0.0f;

        #pragma unroll
        for (int s = 0; s < STAGES - 1; s++) {
            load_stage(s, s * BK);
            asm volatile("cp.async.commit_group;");
        }

        #pragma unroll 1
        for (int kt = 0; kt < NKITER; kt++) {
            asm volatile("cp.async.wait_group 1;" ::: "memory");
            GSYNC();

            const int st = kt % STAGES;
            const uint32_t abase = sbase + (uint32_t)(st * STAGE_B);
            const uint32_t awarp = abase + (uint32_t)((wm * 32) * A_ROW_B) + a_lane_off;
            const uint32_t bwarp = abase + A_STAGE_B + (uint32_t)((wn * 64) * 2) + b_lane_off;

            #pragma unroll
            for (int kc = 0; kc < 4; kc++) {       // four k=16 steps
                uint32_t a[2][4];
                #pragma unroll
                for (int i = 0; i < 2; i++) {
                    const uint32_t addr = awarp + (uint32_t)(i * 16 * A_ROW_B + kc * 32);
                    asm volatile(
                        "ldmatrix.sync.aligned.m8n8.x4.shared.b16 {%0,%1,%2,%3}, [%4];"
                        : "=r"(a[i][0]), "=r"(a[i][1]), "=r"(a[i][2]), "=r"(a[i][3])
                        : "r"(addr));
                }
                uint32_t bfr[8][2];
                #pragma unroll
                for (int jt = 0; jt < 4; jt++) {
                    const uint32_t addr = bwarp + (uint32_t)(kc * 16 * B_ROW_B + jt * 32);
                    asm volatile(
                        "ldmatrix.sync.aligned.m8n8.x4.trans.shared.b16 {%0,%1,%2,%3}, [%4];"
                        : "=r"(bfr[2 * jt][0]), "=r"(bfr[2 * jt][1]),
                          "=r"(bfr[2 * jt + 1][0]), "=r"(bfr[2 * jt + 1][1])
                        : "r"(addr));
                }
                #pragma unroll
                for (int i = 0; i < 2; i++)
                    #pragma unroll
                    for (int j = 0; j < 8; j++) {
                        asm volatile(
                            "mma.sync.aligned.m16n8k16.row.col.f32.f16.f16.f32 "
                            "{%0,%1,%2,%3}, {%4,%5,%6,%7}, {%8,%9}, {%0,%1,%2,%3};"
                            : "+f"(acc[i][j][0]), "+f"(acc[i][j][1]),
                              "+f"(acc[i][j][2]), "+f"(acc[i][j][3])
                            : "r"(a[i][0]), "r"(a[i][1]),
                              "r"(a[i][2]), "r"(a[i][3]),
                              "r"(bfr[j][0]), "r"(bfr[j][1]));
                    }
            }

            const int ls = kt + STAGES - 1;
            if (ls < NKITER) load_stage(ls % STAGES, ls * BK);
            asm volatile("cp.async.commit_group;");
        }

        // epilogue: scale by 1/len, store float2 pairs
        const float* lb = lens + b * Ndim;
        #pragma unroll
        for (int i = 0; i < 2; i++) {
            const int r0 = m0 + wm * 32 + i * 16 + gid;
            const int r1 = r0 + 8;
            const float inv0 = 1.0f / lb[r0];
            const float inv1 = 1.0f / lb[r1];
            float* o0 = out + (size_t)b * Ndim * Hdim + (size_t)r0 * Hdim + h0;
            float* o1 = out + (size_t)b * Ndim * Hdim + (size_t)r1 * Hdim + h0;
            #pragma unroll
            for (int j = 0; j < 8; j++) {
                const int h = wn * 64 + j * 8 + 2 * tq;
                *reinterpret_cast<float2*>(o0 + h) =
                    make_float2(acc[i][j][0] * inv0, acc[i][j][1] * inv0);
                *reinterpret_cast<float2*>(o1 + h) =
                    make_float2(acc[i][j][2] * inv1, acc[i][j][3] * inv1);
            }
        }
    }
}

extern "C" void kernel_launch(void* const* d_in, const int* in_sizes, int n_in,
                              void* d_out, int out_size) {
    const float* doc  = (const float*)d_in[0];   // [8, 4096, 1024]
    const float* map  = (const float*)d_in[1];   // [8, 512, 4096]
    const float* lens = (const float*)d_in[2];   // [8, 512]
    float* out = (float*)d_out;                  // [8, 512, 1024]

    cudaFuncSetAttribute(fused_pool, cudaFuncAttributeMaxDynamicSharedMemorySize, DYN_SMEM);

    reset_flags<<<1, 32>>>();
    fused_pool<<<NCTAS, NTHREADS, DYN_SMEM>>>(doc, map, lens, out);
}